// round 5
// baseline (speedup 1.0000x reference)
#include <cuda_runtime.h>
#include <math.h>

#define B_ 1024
#define V_ 50000
#define H_ 100
#define K_ 200
#define T_ 32768
#define BN_EPS 1e-5f

// GEMM1 config: split-K over V
#define S1  50        // splits
#define VC  1000      // V-chunk per split
#define KB1 20        // k-tile
#define BM1 64        // rows per block

// GEMM2 config
#define KB2 8

// final pass: column chunks of 512
#define NC 98

// ---------------- scratch (__device__ globals; no allocation) ----------------
__device__ float g_p1[S1 * B_ * H_];          // gemm1 split partials (20.5MB)
__device__ float g_h1[B_ * H_];
__device__ float g_h2[B_ * H_];
__device__ float g_mulin[B_ * K_];
__device__ float g_siglin[B_ * K_];
__device__ float g_kA[2 * K_];                // BN affine A for mu (0..199), sig (200..399)
__device__ float g_kC[2 * K_];
__device__ float g_theta[B_ * K_];
__device__ float g_X[(size_t)B_ * V_];        // 204.8MB logits (pre-BN)
__device__ float g_av[V_];
__device__ float g_cv[V_];
__device__ int   g_cnt[V_];
__device__ float g_ep[B_ * NC];
__device__ float g_wp[B_ * NC];

typedef unsigned long long ull;

// packed dual-FMA: bit-identical to two independent fma.rn.f32
__device__ __forceinline__ ull ffma2(ull a, ull b, ull c) {
    ull d;
    asm("fma.rn.f32x2 %0, %1, %2, %3;" : "=l"(d) : "l"(a), "l"(b), "l"(c));
    return d;
}
__device__ __forceinline__ float2 unpack2(ull v) {
    float2 f;
    asm("mov.b64 {%0, %1}, %2;" : "=f"(f.x), "=f"(f.y) : "l"(v));
    return f;
}

__device__ __forceinline__ float softplusf(float x) {
    // stable: matches jax.nn.softplus = logaddexp(x, 0)
    return fmaxf(x, 0.0f) + log1pf(expf(-fabsf(x)));
}

// =====================================================================
// GEMM1: split-K partials of bows[B,V] @ fc1_w[V,H]
// grid (S1 splits, B/BM1 rowblocks), 224 threads (200 compute: 8 rowgrp x 25 colgrp)
// thread tile: 8 rows x 4 cols, FFMA2 (2 cols per packed op)
// A tile stored duplicated (a,a) so LDS.64 yields the packed broadcast.
// =====================================================================
__global__ __launch_bounds__(224) void k_gemm1(const float* __restrict__ bows,
                                               const float* __restrict__ w) {
    __shared__ __align__(16) float2 As2[BM1 * KB1];  // [m][kk] duplicated pairs
    __shared__ __align__(16) float  Ws[KB1 * H_];    // [kk][h]
    const int s   = blockIdx.x;
    const int rb  = blockIdx.y;
    const int tid = threadIdx.x;
    const int rw  = tid / 25;   // row group (0..7) when tid<200
    const int cw  = tid % 25;   // col group (0..24)

    ull acc[8][2];
#pragma unroll
    for (int i = 0; i < 8; i++) { acc[i][0] = 0ull; acc[i][1] = 0ull; }

    int v0 = s * VC;
    for (int it = 0; it < VC / KB1; ++it, v0 += KB1) {
        for (int idx = tid; idx < BM1 * KB1; idx += 224) {
            int m = idx / KB1, kk = idx % KB1;
            float a = bows[(size_t)(rb * BM1 + m) * V_ + v0 + kk];
            As2[idx] = make_float2(a, a);
        }
        for (int idx = tid; idx < KB1 * H_; idx += 224) {
            int kk = idx / H_, h = idx % H_;
            Ws[idx] = w[(size_t)(v0 + kk) * H_ + h];
        }
        __syncthreads();
        if (tid < 200) {
#pragma unroll
            for (int kk = 0; kk < KB1; ++kk) {
                ull ap[8];
#pragma unroll
                for (int i = 0; i < 8; i++)
                    ap[i] = *(const ull*)&As2[(rw * 8 + i) * KB1 + kk];
                ulonglong2 wv = *(const ulonglong2*)&Ws[kk * H_ + cw * 4];
#pragma unroll
                for (int i = 0; i < 8; i++) {
                    acc[i][0] = ffma2(ap[i], wv.x, acc[i][0]);
                    acc[i][1] = ffma2(ap[i], wv.y, acc[i][1]);
                }
            }
        }
        __syncthreads();
    }
    if (tid < 200) {
        float* out = g_p1 + (size_t)s * (B_ * H_);
#pragma unroll
        for (int i = 0; i < 8; i++) {
            int row = rb * BM1 + rw * 8 + i;
#pragma unroll
            for (int j = 0; j < 2; j++) {
                float2 r = unpack2(acc[i][j]);
                out[row * H_ + cw * 4 + 2 * j]     = r.x;
                out[row * H_ + cw * 4 + 2 * j + 1] = r.y;
            }
        }
    }
}

// reduce split partials + bias + softplus -> g_h1
__global__ void k_red1(const float* __restrict__ b1) {
    int i = blockIdx.x * blockDim.x + threadIdx.x;
    if (i >= B_ * H_) return;
    float s = 0.f;
    for (int t = 0; t < S1; t++) s += g_p1[(size_t)t * (B_ * H_) + i];
    s += b1[i % H_];
    g_h1[i] = softplusf(s);
}

// h2 = softplus(h1 @ fc2_w + b)
__global__ void k_h2(const float* __restrict__ w2, const float* __restrict__ b2) {
    int i = blockIdx.x * blockDim.x + threadIdx.x;
    if (i >= B_ * H_) return;
    int b = i / H_, h = i % H_;
    const float* hr = g_h1 + b * H_;
    float s = b2[h];
    for (int j = 0; j < H_; j++) s = fmaf(hr[j], w2[j * H_ + h], s);
    g_h2[i] = softplusf(s);
}

// mu_lin / sig_lin = h2 @ {mu_w, sig_w} + bias
__global__ void k_musig(const float* __restrict__ muw, const float* __restrict__ mub,
                        const float* __restrict__ sgw, const float* __restrict__ sgb) {
    int i = blockIdx.x * blockDim.x + threadIdx.x;
    if (i >= 2 * B_ * K_) return;
    int which = i / (B_ * K_);
    int r = i % (B_ * K_);
    int b = r / K_, k = r % K_;
    const float* hr = g_h2 + b * H_;
    const float* w  = which ? sgw : muw;
    float s = which ? sgb[k] : mub[k];
    for (int j = 0; j < H_; j++) s = fmaf(hr[j], w[j * K_ + k], s);
    (which ? g_siglin : g_mulin)[b * K_ + k] = s;
}

// BN stats over batch for mu_lin (cols 0..199) and sig_lin (cols 200..399)
// shifted sum/sumsq -> cancellation-free biased var (matches jnp.var)
__global__ __launch_bounds__(256) void k_bnk(const float* __restrict__ mug, const float* __restrict__ mubb,
                                             const float* __restrict__ sgg, const float* __restrict__ sgbb) {
    __shared__ float ssum[256], ssq[256];
    int col = blockIdx.x;                 // 0..399
    int c = (col < K_) ? col : col - K_;
    const float* x = (col < K_) ? g_mulin : g_siglin;
    float x0 = x[c];                      // row-0 shift
    float s = 0.f, q = 0.f;
    for (int b = threadIdx.x; b < B_; b += 256) {
        float d = x[b * K_ + c] - x0;
        s += d; q += d * d;
    }
    ssum[threadIdx.x] = s; ssq[threadIdx.x] = q;
    __syncthreads();
    for (int o = 128; o > 0; o >>= 1) {
        if (threadIdx.x < o) {
            ssum[threadIdx.x] += ssum[threadIdx.x + o];
            ssq[threadIdx.x]  += ssq[threadIdx.x + o];
        }
        __syncthreads();
    }
    if (threadIdx.x == 0) {
        float mean_d = ssum[0] * (1.f / B_);
        float var    = ssq[0] * (1.f / B_) - mean_d * mean_d;
        float mean   = x0 + mean_d;
        float g  = (col < K_) ? mug[c]  : sgg[c];
        float bb = (col < K_) ? mubb[c] : sgbb[c];
        float a  = g * rsqrtf(var + BN_EPS);
        g_kA[col] = a;
        g_kC[col] = bb - a * mean;
    }
}

// theta = exp(bn(mu) + exp(0.5*bn(sig)) * eps)
__global__ void k_theta(const float* __restrict__ eps) {
    int i = blockIdx.x * blockDim.x + threadIdx.x;
    if (i >= B_ * K_) return;
    int k = i % K_;
    float m  = fmaf(g_kA[k], g_mulin[i], g_kC[k]);
    float sg = expf(0.5f * fmaf(g_kA[K_ + k], g_siglin[i], g_kC[K_ + k]));
    g_theta[i] = expf(fmaf(sg, eps[i], m));
}

// =====================================================================
// GEMM2: X[B,V] = theta[B,K] @ beta_w[K,V] + beta_b
// grid (ceil(V/128), B/128), 256 threads, 8x8 per-thread tile via FFMA2
// A tile duplicated (a,a); per k-step: 8 LDS.64 + 2 LDS.128 + 32 FFMA2
// =====================================================================
__global__ __launch_bounds__(256) void k_gemm2(const float* __restrict__ bw,
                                               const float* __restrict__ bb) {
    __shared__ __align__(16) float2 As2[128 * KB2]; // [m][kk] duplicated pairs (8KB)
    __shared__ __align__(16) float  Ws[KB2 * 128];  // [kk][c] (4KB)
    const int cb  = blockIdx.x;
    const int rb  = blockIdx.y;
    const int tid = threadIdx.x;
    const int tx  = tid % 16;   // col group: cols tx*8..+7
    const int ty  = tid / 16;   // row group: rows ty*8..+7

    ull acc[8][4];
#pragma unroll
    for (int i = 0; i < 8; i++)
#pragma unroll
        for (int j = 0; j < 4; j++) acc[i][j] = 0ull;

    const int vbase = cb * 128;
    for (int k0 = 0; k0 < K_; k0 += KB2) {
        for (int idx = tid; idx < 128 * KB2; idx += 256) {
            int m = idx / KB2, kk = idx % KB2;
            float a = g_theta[(rb * 128 + m) * K_ + k0 + kk];
            As2[idx] = make_float2(a, a);
        }
        for (int idx = tid; idx < KB2 * 128; idx += 256) {
            int kk = idx / 128, c = idx % 128;
            int v = vbase + c;
            Ws[idx] = (v < V_) ? bw[(size_t)(k0 + kk) * V_ + v] : 0.f;
        }
        __syncthreads();
#pragma unroll
        for (int kk = 0; kk < KB2; kk++) {
            ull ap[8];
#pragma unroll
            for (int i = 0; i < 8; i++)
                ap[i] = *(const ull*)&As2[(ty * 8 + i) * KB2 + kk];
            const ulonglong2* wp = (const ulonglong2*)&Ws[kk * 128 + tx * 8];
            ulonglong2 wA = wp[0];
            ulonglong2 wB = wp[1];
#pragma unroll
            for (int i = 0; i < 8; i++) {
                acc[i][0] = ffma2(ap[i], wA.x, acc[i][0]);
                acc[i][1] = ffma2(ap[i], wA.y, acc[i][1]);
                acc[i][2] = ffma2(ap[i], wB.x, acc[i][2]);
                acc[i][3] = ffma2(ap[i], wB.y, acc[i][3]);
            }
        }
        __syncthreads();
    }
#pragma unroll
    for (int i = 0; i < 8; i++) {
        int row = rb * 128 + ty * 8 + i;
#pragma unroll
        for (int j = 0; j < 4; j++) {
            float2 r = unpack2(acc[i][j]);
            int v = vbase + tx * 8 + 2 * j;
            if (v < V_)     g_X[(size_t)row * V_ + v]     = r.x + bb[v];
            if (v + 1 < V_) g_X[(size_t)row * V_ + v + 1] = r.y + bb[v + 1];
        }
    }
}

// token histogram (int atomics => deterministic)
__global__ void k_zero() {
    int i = blockIdx.x * blockDim.x + threadIdx.x;
    if (i < V_) g_cnt[i] = 0;
}
__global__ void k_hist(const int* __restrict__ tok) {
    int i = blockIdx.x * blockDim.x + threadIdx.x;
    if (i < T_) atomicAdd(&g_cnt[tok[i]], 1);
}

// column stats over X -> per-column BN affine (a_v, c_v)
// block (32,8): 32 consecutive columns (coalesced), 8-way row split
__global__ __launch_bounds__(256) void k_xstats(const float* __restrict__ bg,
                                                const float* __restrict__ bbb) {
    __shared__ float ss[8][32], sq[8][32];
    const int tx = threadIdx.x, ty = threadIdx.y;
    const int v  = blockIdx.x * 32 + tx;
    const bool ok = (v < V_);
    float s = 0.f, q = 0.f, x0 = 0.f;
    if (ok) {
        x0 = g_X[v];   // row-0 shift
        for (int b = ty; b < B_; b += 8) {
            float d = g_X[(size_t)b * V_ + v] - x0;
            s += d; q += d * d;
        }
    }
    ss[ty][tx] = s; sq[ty][tx] = q;
    __syncthreads();
    if (ty == 0 && ok) {
        float S = 0.f, Q = 0.f;
        for (int t = 0; t < 8; t++) { S += ss[t][tx]; Q += sq[t][tx]; }
        float mean_d = S * (1.f / B_);
        float var    = Q * (1.f / B_) - mean_d * mean_d;
        float mean   = x0 + mean_d;
        float a = bg[v] * rsqrtf(var + BN_EPS);
        g_av[v] = a;
        g_cv[v] = bbb[v] - a * mean;
    }
}

// fused pass: per row partials of  E = sum_v exp(y),  W = sum_v cnt_v * y
// grid (NC chunks of 512 cols, B/16 row groups)
__global__ __launch_bounds__(256) void k_final() {
    __shared__ float sa[512], sc[512], scn[512];
    __shared__ float re[8], rw2[8];
    const int chunk = blockIdx.x;
    const int rg    = blockIdx.y;
    const int t     = threadIdx.x;
    const int v0    = chunk * 512;
    for (int i = t; i < 512; i += 256) {
        int v = v0 + i;
        sa[i]  = (v < V_) ? g_av[v] : 0.f;
        sc[i]  = (v < V_) ? g_cv[v] : 0.f;
        scn[i] = (v < V_) ? (float)g_cnt[v] : 0.f;
    }
    __syncthreads();
    for (int rr = 0; rr < 16; ++rr) {
        const int b = rg * 16 + rr;
        const float* xr = g_X + (size_t)b * V_;
        float e = 0.f, w = 0.f;
#pragma unroll
        for (int j = 0; j < 2; j++) {
            int i = t + j * 256;
            int v = v0 + i;
            if (v < V_) {
                float y = fmaf(sa[i], xr[v], sc[i]);
                e += expf(y);
                w = fmaf(scn[i], y, w);
            }
        }
        for (int o = 16; o > 0; o >>= 1) {
            e += __shfl_down_sync(0xffffffffu, e, o);
            w += __shfl_down_sync(0xffffffffu, w, o);
        }
        if ((t & 31) == 0) { re[t >> 5] = e; rw2[t >> 5] = w; }
        __syncthreads();
        if (t == 0) {
            float E = 0.f, W = 0.f;
            for (int q = 0; q < 8; q++) { E += re[q]; W += rw2[q]; }
            g_ep[b * NC + chunk] = E;
            g_wp[b * NC + chunk] = W;
        }
        __syncthreads();
    }
}

// loglik[b] = W[b] - T * log(E[b])
__global__ void k_finish(float* __restrict__ out) {
    int b = blockIdx.x * blockDim.x + threadIdx.x;
    if (b >= B_) return;
    float E = 0.f, W = 0.f;
    for (int c = 0; c < NC; c++) { E += g_ep[b * NC + c]; W += g_wp[b * NC + c]; }
    out[b] = W - (float)T_ * logf(E);
}

extern "C" void kernel_launch(void* const* d_in, const int* in_sizes, int n_in,
                              void* d_out, int out_size) {
    const float* bows = (const float*)d_in[0];
    const float* eps  = (const float*)d_in[1];
    const int*   tok  = (const int*)  d_in[2];
    const float* fc1w = (const float*)d_in[3];
    const float* fc1b = (const float*)d_in[4];
    const float* fc2w = (const float*)d_in[5];
    const float* fc2b = (const float*)d_in[6];
    const float* muw  = (const float*)d_in[7];
    const float* mub  = (const float*)d_in[8];
    const float* bnmg = (const float*)d_in[9];
    const float* bnmb = (const float*)d_in[10];
    const float* sgw  = (const float*)d_in[11];
    const float* sgb  = (const float*)d_in[12];
    const float* bnsg = (const float*)d_in[13];
    const float* bnsb = (const float*)d_in[14];
    const float* btw  = (const float*)d_in[15];
    const float* btb  = (const float*)d_in[16];
    const float* bnbg = (const float*)d_in[17];
    const float* bnbb = (const float*)d_in[18];
    float* out = (float*)d_out;

    k_gemm1 <<<dim3(S1, B_ / BM1), 224>>>(bows, fc1w);
    k_red1  <<<(B_ * H_ + 255) / 256, 256>>>(fc1b);
    k_h2    <<<(B_ * H_ + 255) / 256, 256>>>(fc2w, fc2b);
    k_musig <<<(2 * B_ * K_ + 255) / 256, 256>>>(muw, mub, sgw, sgb);
    k_bnk   <<<2 * K_, 256>>>(bnmg, bnmb, bnsg, bnsb);
    k_theta <<<(B_ * K_ + 255) / 256, 256>>>(eps);
    k_gemm2 <<<dim3((V_ + 127) / 128, B_ / 128), 256>>>(btw, btb);
    k_zero  <<<(V_ + 255) / 256, 256>>>();
    k_hist  <<<(T_ + 255) / 256, 256>>>(tok);
    k_xstats<<<(V_ + 31) / 32, dim3(32, 8)>>>(bnbg, bnbb);
    k_final <<<dim3(NC, B_ / 16), 256>>>();
    k_finish<<<(B_ + 255) / 256, 256>>>(out);
}

// round 6
// speedup vs baseline: 1.0050x; 1.0050x over previous
#include <cuda_runtime.h>
#include <math.h>

#define B_ 1024
#define V_ 50000
#define H_ 100
#define K_ 200
#define T_ 32768
#define BN_EPS 1e-5f

// GEMM1 config: split-K over V
#define S1  50        // splits
#define VC  1000      // V-chunk per split
#define KB1 20        // k-tile
#define BM1 64        // rows per block

// GEMM2 config
#define KB2 8

// final pass: column chunks of 512
#define NC 98

// ---------------- scratch (__device__ globals; no allocation) ----------------
__device__ float g_p1[S1 * B_ * H_];          // gemm1 split partials (20.5MB)
__device__ float g_h1[B_ * H_];
__device__ float g_h2[B_ * H_];
__device__ float g_mulin[B_ * K_];
__device__ float g_siglin[B_ * K_];
__device__ float g_kA[2 * K_];                // BN affine A for mu (0..199), sig (200..399)
__device__ float g_kC[2 * K_];
__device__ float g_theta[B_ * K_];
__device__ float g_X[(size_t)B_ * V_];        // 204.8MB logits (pre-BN)
__device__ float g_av[V_];
__device__ float g_cv[V_];
__device__ int   g_cnt[V_];
__device__ float g_ep[B_ * NC];
__device__ float g_wp[B_ * NC];

typedef unsigned long long ull;

// packed dual-FMA: bit-identical to two independent fma.rn.f32
__device__ __forceinline__ ull ffma2(ull a, ull b, ull c) {
    ull d;
    asm("fma.rn.f32x2 %0, %1, %2, %3;" : "=l"(d) : "l"(a), "l"(b), "l"(c));
    return d;
}
__device__ __forceinline__ float2 unpack2(ull v) {
    float2 f;
    asm("mov.b64 {%0, %1}, %2;" : "=f"(f.x), "=f"(f.y) : "l"(v));
    return f;
}

__device__ __forceinline__ float softplusf(float x) {
    // stable: matches jax.nn.softplus = logaddexp(x, 0)
    return fmaxf(x, 0.0f) + log1pf(expf(-fabsf(x)));
}

// FMA-pipe exp: valid for |y| < ~80 (here |y| <= ~40). rel err ~5e-8.
__device__ __forceinline__ float exp_fast(float y) {
    const float LOG2E = 1.4426950408889634f;
    const float MAGIC = 12582912.0f;      // 1.5 * 2^23
    float t = y * LOG2E;
    float z = t + MAGIC;
    int   n = __float_as_int(z) - 0x4B400000;
    float f = t - (z - MAGIC);            // |f| <= 0.5 (+eps)
    // 2^f = exp(ln2 * f), Taylor deg 7
    float p = 1.5252733e-5f;
    p = fmaf(p, f, 1.5403531e-4f);
    p = fmaf(p, f, 1.3333558e-3f);
    p = fmaf(p, f, 9.6181291e-3f);
    p = fmaf(p, f, 5.5504109e-2f);
    p = fmaf(p, f, 2.4022651e-1f);
    p = fmaf(p, f, 6.9314718e-1f);
    p = fmaf(p, f, 1.0f);
    return p * __int_as_float((n + 127) << 23);
}

// =====================================================================
// GEMM1: split-K partials of bows[B,V] @ fc1_w[V,H]
// grid (S1 splits, B/BM1 rowblocks), 224 threads (200 compute: 8 rowgrp x 25 colgrp)
// thread tile: 8 rows x 4 cols, FFMA2. A tile duplicated (a,a); paired-kk
// LDS.128 fetches both k-step broadcasts at once (76% FFMA2 issue mix).
// =====================================================================
__global__ __launch_bounds__(224) void k_gemm1(const float* __restrict__ bows,
                                               const float* __restrict__ w) {
    __shared__ __align__(16) float2 As2[BM1 * KB1];  // [m][kk] duplicated pairs (10.2KB)
    __shared__ __align__(16) float  Ws[KB1 * H_];    // [kk][h] (8KB)
    const int s   = blockIdx.x;
    const int rb  = blockIdx.y;
    const int tid = threadIdx.x;
    const int rw  = tid / 25;   // row group (0..7) when tid<200
    const int cw  = tid % 25;   // col group (0..24)

    ull acc[8][2];
#pragma unroll
    for (int i = 0; i < 8; i++) { acc[i][0] = 0ull; acc[i][1] = 0ull; }

    int v0 = s * VC;
    for (int it = 0; it < VC / KB1; ++it, v0 += KB1) {
        // A fill: float2 global loads, duplicated into pairs
        for (int idx = tid; idx < BM1 * (KB1 / 2); idx += 224) {
            int m = idx / (KB1 / 2), kp = idx % (KB1 / 2);
            float2 a = *(const float2*)&bows[(size_t)(rb * BM1 + m) * V_ + v0 + 2 * kp];
            As2[m * KB1 + 2 * kp]     = make_float2(a.x, a.x);
            As2[m * KB1 + 2 * kp + 1] = make_float2(a.y, a.y);
        }
        // W fill: float2 (H_=100 even, rows 8B aligned)
        for (int idx = tid; idx < KB1 * (H_ / 2); idx += 224) {
            int kk = idx / (H_ / 2), h2 = idx % (H_ / 2);
            *(float2*)&Ws[kk * H_ + 2 * h2] =
                *(const float2*)&w[(size_t)(v0 + kk) * H_ + 2 * h2];
        }
        __syncthreads();
        if (tid < 200) {
#pragma unroll
            for (int kp = 0; kp < KB1; kp += 2) {
                ulonglong2 ap[8];
#pragma unroll
                for (int i = 0; i < 8; i++)
                    ap[i] = *(const ulonglong2*)&As2[(rw * 8 + i) * KB1 + kp];
                ulonglong2 wv0 = *(const ulonglong2*)&Ws[kp * H_ + cw * 4];
                ulonglong2 wv1 = *(const ulonglong2*)&Ws[(kp + 1) * H_ + cw * 4];
#pragma unroll
                for (int i = 0; i < 8; i++) {
                    acc[i][0] = ffma2(ap[i].x, wv0.x, acc[i][0]);
                    acc[i][1] = ffma2(ap[i].x, wv0.y, acc[i][1]);
                    acc[i][0] = ffma2(ap[i].y, wv1.x, acc[i][0]);
                    acc[i][1] = ffma2(ap[i].y, wv1.y, acc[i][1]);
                }
            }
        }
        __syncthreads();
    }
    if (tid < 200) {
        float* out = g_p1 + (size_t)s * (B_ * H_);
#pragma unroll
        for (int i = 0; i < 8; i++) {
            int row = rb * BM1 + rw * 8 + i;
#pragma unroll
            for (int j = 0; j < 2; j++) {
                float2 r = unpack2(acc[i][j]);
                out[row * H_ + cw * 4 + 2 * j]     = r.x;
                out[row * H_ + cw * 4 + 2 * j + 1] = r.y;
            }
        }
    }
}

// reduce split partials + bias + softplus -> g_h1
__global__ void k_red1(const float* __restrict__ b1) {
    int i = blockIdx.x * blockDim.x + threadIdx.x;
    if (i >= B_ * H_) return;
    float s = 0.f;
    for (int t = 0; t < S1; t++) s += g_p1[(size_t)t * (B_ * H_) + i];
    s += b1[i % H_];
    g_h1[i] = softplusf(s);
}

// h2 = softplus(h1 @ fc2_w + b)
__global__ void k_h2(const float* __restrict__ w2, const float* __restrict__ b2) {
    int i = blockIdx.x * blockDim.x + threadIdx.x;
    if (i >= B_ * H_) return;
    int b = i / H_, h = i % H_;
    const float* hr = g_h1 + b * H_;
    float s = b2[h];
    for (int j = 0; j < H_; j++) s = fmaf(hr[j], w2[j * H_ + h], s);
    g_h2[i] = softplusf(s);
}

// mu_lin / sig_lin = h2 @ {mu_w, sig_w} + bias
__global__ void k_musig(const float* __restrict__ muw, const float* __restrict__ mub,
                        const float* __restrict__ sgw, const float* __restrict__ sgb) {
    int i = blockIdx.x * blockDim.x + threadIdx.x;
    if (i >= 2 * B_ * K_) return;
    int which = i / (B_ * K_);
    int r = i % (B_ * K_);
    int b = r / K_, k = r % K_;
    const float* hr = g_h2 + b * H_;
    const float* w  = which ? sgw : muw;
    float s = which ? sgb[k] : mub[k];
    for (int j = 0; j < H_; j++) s = fmaf(hr[j], w[j * K_ + k], s);
    (which ? g_siglin : g_mulin)[b * K_ + k] = s;
}

// BN stats over batch for mu_lin (cols 0..199) and sig_lin (cols 200..399)
// shifted sum/sumsq -> cancellation-free biased var (matches jnp.var)
__global__ __launch_bounds__(256) void k_bnk(const float* __restrict__ mug, const float* __restrict__ mubb,
                                             const float* __restrict__ sgg, const float* __restrict__ sgbb) {
    __shared__ float ssum[256], ssq[256];
    int col = blockIdx.x;                 // 0..399
    int c = (col < K_) ? col : col - K_;
    const float* x = (col < K_) ? g_mulin : g_siglin;
    float x0 = x[c];                      // row-0 shift
    float s = 0.f, q = 0.f;
    for (int b = threadIdx.x; b < B_; b += 256) {
        float d = x[b * K_ + c] - x0;
        s += d; q += d * d;
    }
    ssum[threadIdx.x] = s; ssq[threadIdx.x] = q;
    __syncthreads();
    for (int o = 128; o > 0; o >>= 1) {
        if (threadIdx.x < o) {
            ssum[threadIdx.x] += ssum[threadIdx.x + o];
            ssq[threadIdx.x]  += ssq[threadIdx.x + o];
        }
        __syncthreads();
    }
    if (threadIdx.x == 0) {
        float mean_d = ssum[0] * (1.f / B_);
        float var    = ssq[0] * (1.f / B_) - mean_d * mean_d;
        float mean   = x0 + mean_d;
        float g  = (col < K_) ? mug[c]  : sgg[c];
        float bb = (col < K_) ? mubb[c] : sgbb[c];
        float a  = g * rsqrtf(var + BN_EPS);
        g_kA[col] = a;
        g_kC[col] = bb - a * mean;
    }
}

// theta = exp(bn(mu) + exp(0.5*bn(sig)) * eps)
__global__ void k_theta(const float* __restrict__ eps) {
    int i = blockIdx.x * blockDim.x + threadIdx.x;
    if (i >= B_ * K_) return;
    int k = i % K_;
    float m  = fmaf(g_kA[k], g_mulin[i], g_kC[k]);
    float sg = expf(0.5f * fmaf(g_kA[K_ + k], g_siglin[i], g_kC[K_ + k]));
    g_theta[i] = expf(fmaf(sg, eps[i], m));
}

// =====================================================================
// GEMM2: X[B,V] = theta[B,K] @ beta_w[K,V] + beta_b
// grid (ceil(V/128), B/128), 256 threads, 8x8 per-thread tile via FFMA2
// Paired-kk: per 2 k-steps 8 LDS.128(A) + 4 LDS.128(W) + 64 FFMA2 (84% mix)
// =====================================================================
__global__ __launch_bounds__(256) void k_gemm2(const float* __restrict__ bw,
                                               const float* __restrict__ bb) {
    __shared__ __align__(16) float2 As2[128 * KB2]; // [m][kk] duplicated pairs (8KB)
    __shared__ __align__(16) float  Ws[KB2 * 128];  // [kk][c] (4KB)
    const int cb  = blockIdx.x;
    const int rb  = blockIdx.y;
    const int tid = threadIdx.x;
    const int tx  = tid % 16;   // col group: cols tx*8..+7
    const int ty  = tid / 16;   // row group: rows ty*8..+7

    ull acc[8][4];
#pragma unroll
    for (int i = 0; i < 8; i++)
#pragma unroll
        for (int j = 0; j < 4; j++) acc[i][j] = 0ull;

    const int vbase = cb * 128;
    for (int k0 = 0; k0 < K_; k0 += KB2) {
        // A fill: float2 loads from theta, duplicated into pairs (2 per thread)
        for (int idx = tid; idx < 128 * (KB2 / 2); idx += 256) {
            int m = idx / (KB2 / 2), kp = idx % (KB2 / 2);
            float2 a = *(const float2*)&g_theta[(rb * 128 + m) * K_ + k0 + 2 * kp];
            As2[m * KB2 + 2 * kp]     = make_float2(a.x, a.x);
            As2[m * KB2 + 2 * kp + 1] = make_float2(a.y, a.y);
        }
        // W fill: float4 (V_%4==0 so rows 16B aligned), guarded tail
        for (int idx = tid; idx < KB2 * 32; idx += 256) {
            int kk = idx / 32, c4 = idx % 32;
            int v = vbase + c4 * 4;
            float4 val;
            if (v + 3 < V_) {
                val = *(const float4*)&bw[(size_t)(k0 + kk) * V_ + v];
            } else {
                val.x = (v     < V_) ? bw[(size_t)(k0 + kk) * V_ + v]     : 0.f;
                val.y = (v + 1 < V_) ? bw[(size_t)(k0 + kk) * V_ + v + 1] : 0.f;
                val.z = (v + 2 < V_) ? bw[(size_t)(k0 + kk) * V_ + v + 2] : 0.f;
                val.w = 0.f;
            }
            *(float4*)&Ws[kk * 128 + c4 * 4] = val;
        }
        __syncthreads();
#pragma unroll
        for (int kp = 0; kp < KB2; kp += 2) {
            ulonglong2 ap[8];
#pragma unroll
            for (int i = 0; i < 8; i++)
                ap[i] = *(const ulonglong2*)&As2[(ty * 8 + i) * KB2 + kp];
            ulonglong2 wA0 = *(const ulonglong2*)&Ws[kp * 128 + tx * 8];
            ulonglong2 wA1 = *(const ulonglong2*)&Ws[kp * 128 + tx * 8 + 4];
            ulonglong2 wB0 = *(const ulonglong2*)&Ws[(kp + 1) * 128 + tx * 8];
            ulonglong2 wB1 = *(const ulonglong2*)&Ws[(kp + 1) * 128 + tx * 8 + 4];
#pragma unroll
            for (int i = 0; i < 8; i++) {
                acc[i][0] = ffma2(ap[i].x, wA0.x, acc[i][0]);
                acc[i][1] = ffma2(ap[i].x, wA0.y, acc[i][1]);
                acc[i][2] = ffma2(ap[i].x, wA1.x, acc[i][2]);
                acc[i][3] = ffma2(ap[i].x, wA1.y, acc[i][3]);
                acc[i][0] = ffma2(ap[i].y, wB0.x, acc[i][0]);
                acc[i][1] = ffma2(ap[i].y, wB0.y, acc[i][1]);
                acc[i][2] = ffma2(ap[i].y, wB1.x, acc[i][2]);
                acc[i][3] = ffma2(ap[i].y, wB1.y, acc[i][3]);
            }
        }
        __syncthreads();
    }
#pragma unroll
    for (int i = 0; i < 8; i++) {
        int row = rb * 128 + ty * 8 + i;
#pragma unroll
        for (int j = 0; j < 4; j++) {
            float2 r = unpack2(acc[i][j]);
            int v = vbase + tx * 8 + 2 * j;
            if (v < V_)     g_X[(size_t)row * V_ + v]     = r.x + bb[v];
            if (v + 1 < V_) g_X[(size_t)row * V_ + v + 1] = r.y + bb[v + 1];
        }
    }
}

// token histogram (int atomics => deterministic)
__global__ void k_zero() {
    int i = blockIdx.x * blockDim.x + threadIdx.x;
    if (i < V_) g_cnt[i] = 0;
}
__global__ void k_hist(const int* __restrict__ tok) {
    int i = blockIdx.x * blockDim.x + threadIdx.x;
    if (i < T_) atomicAdd(&g_cnt[tok[i]], 1);
}

// column stats over X -> per-column BN affine (a_v, c_v)
// block (32,8): 32 consecutive columns (coalesced), 8-way row split
__global__ __launch_bounds__(256) void k_xstats(const float* __restrict__ bg,
                                                const float* __restrict__ bbb) {
    __shared__ float ss[8][32], sq[8][32];
    const int tx = threadIdx.x, ty = threadIdx.y;
    const int v  = blockIdx.x * 32 + tx;
    const bool ok = (v < V_);
    float s = 0.f, q = 0.f, x0 = 0.f;
    if (ok) {
        x0 = g_X[v];   // row-0 shift
        for (int b = ty; b < B_; b += 8) {
            float d = g_X[(size_t)b * V_ + v] - x0;
            s += d; q += d * d;
        }
    }
    ss[ty][tx] = s; sq[ty][tx] = q;
    __syncthreads();
    if (ty == 0 && ok) {
        float S = 0.f, Q = 0.f;
        for (int t = 0; t < 8; t++) { S += ss[t][tx]; Q += sq[t][tx]; }
        float mean_d = S * (1.f / B_);
        float var    = Q * (1.f / B_) - mean_d * mean_d;
        float mean   = x0 + mean_d;
        float a = bg[v] * rsqrtf(var + BN_EPS);
        g_av[v] = a;
        g_cv[v] = bbb[v] - a * mean;
    }
}

// fused pass: per row partials of  E = sum_v exp(y),  W = sum_v cnt_v * y
// grid (NC chunks of 512 cols, B/16 row groups); 512 thr = 16 warps,
// one warp per row -> no in-loop block syncs; exp on FMA pipe.
__global__ __launch_bounds__(512) void k_final() {
    __shared__ float sa[512], sc[512], scn[512];
    const int chunk = blockIdx.x;
    const int rg    = blockIdx.y;
    const int t     = threadIdx.x;
    const int v0    = chunk * 512;
    {
        int v = v0 + t;
        sa[t]  = (v < V_) ? g_av[v] : 0.f;
        sc[t]  = (v < V_) ? g_cv[v] : 0.f;
        scn[t] = (v < V_) ? (float)g_cnt[v] : 0.f;
    }
    __syncthreads();
    const int wrp  = t >> 5;
    const int lane = t & 31;
    const int b    = rg * 16 + wrp;
    const float* xr = g_X + (size_t)b * V_;
    float e = 0.f, wsum = 0.f;
#pragma unroll
    for (int j = 0; j < 16; j++) {
        int i = lane + j * 32;
        int v = v0 + i;
        if (v < V_) {
            float y = fmaf(sa[i], xr[v], sc[i]);
            e += exp_fast(y);
            wsum = fmaf(scn[i], y, wsum);
        }
    }
#pragma unroll
    for (int o = 16; o > 0; o >>= 1) {
        e    += __shfl_down_sync(0xffffffffu, e, o);
        wsum += __shfl_down_sync(0xffffffffu, wsum, o);
    }
    if (lane == 0) {
        g_ep[b * NC + chunk] = e;
        g_wp[b * NC + chunk] = wsum;
    }
}

// loglik[b] = W[b] - T * log(E[b])
__global__ void k_finish(float* __restrict__ out) {
    int b = blockIdx.x * blockDim.x + threadIdx.x;
    if (b >= B_) return;
    float E = 0.f, W = 0.f;
    for (int c = 0; c < NC; c++) { E += g_ep[b * NC + c]; W += g_wp[b * NC + c]; }
    out[b] = W - (float)T_ * logf(E);
}

extern "C" void kernel_launch(void* const* d_in, const int* in_sizes, int n_in,
                              void* d_out, int out_size) {
    const float* bows = (const float*)d_in[0];
    const float* eps  = (const float*)d_in[1];
    const int*   tok  = (const int*)  d_in[2];
    const float* fc1w = (const float*)d_in[3];
    const float* fc1b = (const float*)d_in[4];
    const float* fc2w = (const float*)d_in[5];
    const float* fc2b = (const float*)d_in[6];
    const float* muw  = (const float*)d_in[7];
    const float* mub  = (const float*)d_in[8];
    const float* bnmg = (const float*)d_in[9];
    const float* bnmb = (const float*)d_in[10];
    const float* sgw  = (const float*)d_in[11];
    const float* sgb  = (const float*)d_in[12];
    const float* bnsg = (const float*)d_in[13];
    const float* bnsb = (const float*)d_in[14];
    const float* btw  = (const float*)d_in[15];
    const float* btb  = (const float*)d_in[16];
    const float* bnbg = (const float*)d_in[17];
    const float* bnbb = (const float*)d_in[18];
    float* out = (float*)d_out;

    k_gemm1 <<<dim3(S1, B_ / BM1), 224>>>(bows, fc1w);
    k_red1  <<<(B_ * H_ + 255) / 256, 256>>>(fc1b);
    k_h2    <<<(B_ * H_ + 255) / 256, 256>>>(fc2w, fc2b);
    k_musig <<<(2 * B_ * K_ + 255) / 256, 256>>>(muw, mub, sgw, sgb);
    k_bnk   <<<2 * K_, 256>>>(bnmg, bnmb, bnsg, bnsb);
    k_theta <<<(B_ * K_ + 255) / 256, 256>>>(eps);
    k_gemm2 <<<dim3((V_ + 127) / 128, B_ / 128), 256>>>(btw, btb);
    k_zero  <<<(V_ + 255) / 256, 256>>>();
    k_hist  <<<(T_ + 255) / 256, 256>>>(tok);
    k_xstats<<<(V_ + 31) / 32, dim3(32, 8)>>>(bnbg, bnbb);
    k_final <<<dim3(NC, B_ / 16), 512>>>();
    k_finish<<<(B_ + 255) / 256, 256>>>(out);
}